// round 16
// baseline (speedup 1.0000x reference)
#include <cuda_runtime.h>

#define Bsz   128
#define Lseq  4096
#define Hd    64
#define G3    192
#define IN2H  128
#define NCLS  230
#define BL    (Bsz * Lseq)
#define NTILE 64           // 64 steps per gx tile
#define NGEMM (4 * Bsz * NTILE)   // 32768 gemm blocks per layer

typedef unsigned long long ull;

// Scratch (allocation-free rule)
__device__ float g_gx[(size_t)2 * BL * G3];     // [dir][b][t][192] (~805 MB)
__device__ float g_bufA[(size_t)BL * IN2H];     // ~268 MB
__device__ float g_bufB[(size_t)BL * IN2H];     // ~268 MB
__device__ int   g_flags[3 * 2 * Bsz * NTILE];  // per (layer-1, d, b, tile)

// ---------------- helpers ----------------
__device__ __forceinline__ ull fma2(ull a, ull b, ull c) {
    ull d;
    asm("fma.rn.f32x2 %0, %1, %2, %3;" : "=l"(d) : "l"(a), "l"(b), "l"(c));
    return d;
}
__device__ __forceinline__ float2 u2f2(ull v) {
    float2 f;
    asm("mov.b64 {%0, %1}, %2;" : "=f"(f.x), "=f"(f.y) : "l"(v));
    return f;
}
__device__ __forceinline__ float tanh_fast(float x) {
    float y;
    asm("tanh.approx.f32 %0, %1;" : "=f"(y) : "f"(x));
    return y;
}
__device__ __forceinline__ float sigm_fast(float x) {
    return fmaf(0.5f, tanh_fast(0.5f * x), 0.5f);
}
__device__ __forceinline__ unsigned smem_u32(const void* p) {
    return (unsigned)__cvta_generic_to_shared(p);
}
__device__ __forceinline__ void cp_async16(unsigned dst, const void* src) {
    asm volatile("cp.async.cg.shared.global [%0], [%1], 16;"
                 :: "r"(dst), "l"(src));
}
__device__ __forceinline__ void cp_commit() {
    asm volatile("cp.async.commit_group;");
}
template <int N>
__device__ __forceinline__ void cp_wait() {
    asm volatile("cp.async.wait_group %0;" :: "n"(N));
}
__device__ __forceinline__ void wait_flag(const int* p) {
    int v;
    do {
        asm volatile("ld.acquire.gpu.global.s32 %0, [%1];"
                     : "=r"(v) : "l"(p));
    } while (v < 2);
}

__global__ void zero_flags_kernel() {
    int i = blockIdx.x * 256 + threadIdx.x;
    if (i < 3 * 2 * Bsz * NTILE) g_flags[i] = 0;
}

// ---------------- layer-0 scan (R14 core, x fused, no flags) --------------
__global__ void __launch_bounds__(256)
scan0_kernel(const float* __restrict__ w_hh,
             const float* __restrict__ b_hh,
             const float* __restrict__ x,
             const float* __restrict__ w_ih0,
             const float* __restrict__ b_ih,
             float* __restrict__ out_g) {
    const int b = blockIdx.x;
    const int tid = threadIdx.x;
    const int d = tid >> 7;
    const int j = (tid & 127) >> 1;
    const int half = tid & 1;
    const unsigned barid = 1 + d;

    const size_t base = (size_t)d * G3;   // layer 0
    const ull* Wr = (const ull*)w_hh + (base + j) * 32 + half * 16;
    const ull* Wz = (const ull*)w_hh + (base + 64 + j) * 32 + half * 16;
    const ull* Wn = (const ull*)w_hh + (base + 128 + j) * 32 + half * 16;
    ull wr[16], wz[16], wn[16];
#pragma unroll
    for (int i = 0; i < 16; i++) { wr[i] = Wr[i]; wz[i] = Wz[i]; wn[i] = Wn[i]; }
    const float br = b_hh[base + j];
    const float bz = b_hh[base + 64 + j];
    const float bn = b_hh[base + 128 + j];

    __shared__ __align__(16) float h_s[2][2][Hd];
    if ((tid & 127) < Hd) h_s[d][0][tid & 127] = 0.0f;
    float hreg = 0.0f;

    const int t0 = (d == 0) ? 0 : (Lseq - 1);
    const int tstep = (d == 0) ? 1 : -1;

    float w0r = 0.f, w0z = 0.f, w0n = 0.f, c0r = 0.f, c0z = 0.f, c0n = 0.f;
    const float* xs = x + (size_t)b * Lseq + t0;
    if (half == 0) {
        w0r = w_ih0[d * G3 + j];
        w0z = w_ih0[d * G3 + 64 + j];
        w0n = w_ih0[d * G3 + 128 + j];
        c0r = b_ih[(size_t)d * G3 + j];
        c0z = b_ih[(size_t)d * G3 + 64 + j];
        c0n = b_ih[(size_t)d * G3 + 128 + j];
    }
    float* outp = out_g + (size_t)b * Lseq * IN2H + d * Hd + j;

    asm volatile("bar.sync %0, %1;" :: "r"(barid), "r"(128) : "memory");

    float qr0 = 0.f, qr1 = 0.f;
    if (half == 0) { qr0 = xs[0]; qr1 = xs[(long)tstep]; }

#define SCAN0_STEP(PR, S)                                                     \
    {                                                                         \
        const int s_ = (S);                                                   \
        float rawr = qr##PR;                                                  \
        const int sp_ = s_ + 2;                                               \
        if (half == 0 && sp_ < Lseq) qr##PR = xs[(long)sp_ * tstep];          \
        const ulonglong2* h4_ =                                               \
            (const ulonglong2*)(h_s[d][PR] + half * 32);                      \
        ull r0 = 0, r1 = 0, z0 = 0, z1 = 0, n0 = 0, n1 = 0;                   \
        _Pragma("unroll")                                                     \
        for (int i = 0; i < 4; i++) {                                         \
            ulonglong2 u = h4_[2 * i];                                        \
            ulonglong2 v = h4_[2 * i + 1];                                    \
            r0 = fma2(wr[4 * i + 0], u.x, r0);                                \
            r1 = fma2(wr[4 * i + 1], u.y, r1);                                \
            z0 = fma2(wz[4 * i + 0], u.x, z0);                                \
            z1 = fma2(wz[4 * i + 1], u.y, z1);                                \
            n0 = fma2(wn[4 * i + 0], u.x, n0);                                \
            n1 = fma2(wn[4 * i + 1], u.y, n1);                                \
            r0 = fma2(wr[4 * i + 2], v.x, r0);                                \
            r1 = fma2(wr[4 * i + 3], v.y, r1);                                \
            z0 = fma2(wz[4 * i + 2], v.x, z0);                                \
            z1 = fma2(wz[4 * i + 3], v.y, z1);                                \
            n0 = fma2(wn[4 * i + 2], v.x, n0);                                \
            n1 = fma2(wn[4 * i + 3], v.y, n1);                                \
        }                                                                     \
        float2 fr0 = u2f2(r0), fr1 = u2f2(r1);                                \
        float2 fz0 = u2f2(z0), fz1 = u2f2(z1);                                \
        float2 fn0 = u2f2(n0), fn1 = u2f2(n1);                                \
        float pgr = (fr0.x + fr0.y) + (fr1.x + fr1.y);                        \
        float pgz = (fz0.x + fz0.y) + (fz1.x + fz1.y);                        \
        float pgn = (fn0.x + fn0.y) + (fn1.x + fn1.y);                        \
        pgr += __shfl_xor_sync(0xFFFFFFFFu, pgr, 1);                          \
        pgz += __shfl_xor_sync(0xFFFFFFFFu, pgz, 1);                          \
        pgn += __shfl_xor_sync(0xFFFFFFFFu, pgn, 1);                          \
        if (half == 0) {                                                      \
            float gxr = fmaf(rawr, w0r, c0r);                                 \
            float gxz = fmaf(rawr, w0z, c0z);                                 \
            float gxn = fmaf(rawr, w0n, c0n);                                 \
            float r_ = sigm_fast(gxr + pgr + br);                             \
            float z_ = sigm_fast(gxz + pgz + bz);                             \
            float n_ = tanh_fast(fmaf(r_, pgn + bn, gxn));                    \
            float hn = fmaf(z_, hreg - n_, n_);                               \
            hreg = hn;                                                        \
            h_s[d][1 - (PR)][j] = hn;                                         \
            outp[(size_t)(t0 + s_ * tstep) * IN2H] = hn;                      \
        }                                                                     \
        asm volatile("bar.sync %0, %1;" :: "r"(barid), "r"(128) : "memory");  \
    }

#pragma unroll 1
    for (int s0 = 0; s0 < Lseq; s0 += 2) {
        SCAN0_STEP(0, s0)
        SCAN0_STEP(1, s0 + 1)
    }
#undef SCAN0_STEP
}

// ---------------- fused layer kernel (layers 1..3) ------------------------
// grid = Bsz scan blocks (bid 0..127, scheduled first) + NGEMM gemm blocks.
// GEMM blocks produce gx tile-major (t-reversed for dir1) and post flags;
// scan blocks consume gx, spinning on a flag only when their 2-step
// register prefetch crosses a 64-step tile boundary.
__global__ void __launch_bounds__(256, 2)
layer_kernel(const float* __restrict__ w_hh,
             const float* __restrict__ b_hh,
             const float* __restrict__ b_ih,
             const float* __restrict__ w_ih,
             const float* __restrict__ inp,
             float* __restrict__ out_g,
             int layer) {
    __shared__ __align__(16) ull a_s[2][64][18];
    __shared__ __align__(16) ull b_s[2][96][18];
    __shared__ __align__(16) float h_s[2][2][Hd];

    const int tid = threadIdx.x;

    if (blockIdx.x >= Bsz) {
        // =================== GEMM producer (R14 core) ===================
        const int gid = blockIdx.x - Bsz;
        const int x4 = gid & 3;
        const int d  = x4 & 1;
        const int c0 = (x4 >> 1) * 96;
        const int y  = gid >> 2;
        const int b  = y & 127;        // batch fastest -> tile-major order
        const int tch = y >> 7;        // 0..63
        const int t0 = (d ? (NTILE - 1 - tch) : tch) * 64;
        const size_t row0 = (size_t)b * Lseq + t0;
        const int tx = tid & 15;
        const int ty = tid >> 4;

        const ull* inp2 = (const ull*)inp;
        const ull* w2g =
            (const ull*)(w_ih + ((size_t)(layer - 1) * 2 + d) * G3 * IN2H);

        unsigned a_dst[2], b_dst[3];
        const ull* a_src[2];
        const ull* b_src[3];
#pragma unroll
        for (int it = 0; it < 2; it++) {
            int lin = tid + it * 256;
            int r = lin >> 3, pp = lin & 7;
            a_dst[it] = smem_u32(&a_s[0][r][2 * pp]);
            a_src[it] = inp2 + (row0 + r) * 64 + 2 * pp;
        }
#pragma unroll
        for (int it = 0; it < 3; it++) {
            int lin = tid + it * 256;
            int cc = lin >> 3, pp = lin & 7;
            b_dst[it] = smem_u32(&b_s[0][cc][2 * pp]);
            b_src[it] = w2g + (size_t)(c0 + cc) * 64 + 2 * pp;
        }
        const unsigned A_BUF_BYTES = 64 * 18 * 8;
        const unsigned B_BUF_BYTES = 96 * 18 * 8;

        ull acc[4][6];
#pragma unroll
        for (int i = 0; i < 4; i++)
#pragma unroll
            for (int j2 = 0; j2 < 6; j2++) acc[i][j2] = 0ULL;

#pragma unroll
        for (int it = 0; it < 2; it++) cp_async16(a_dst[it], a_src[it]);
#pragma unroll
        for (int it = 0; it < 3; it++) cp_async16(b_dst[it], b_src[it]);
        cp_commit();

#pragma unroll
        for (int ch = 0; ch < 4; ch++) {
            const int buf = ch & 1;
            if (ch < 3) {
                const int nb = (ch + 1) & 1;
#pragma unroll
                for (int it = 0; it < 2; it++)
                    cp_async16(a_dst[it] + nb * A_BUF_BYTES,
                               a_src[it] + (ch + 1) * 16);
#pragma unroll
                for (int it = 0; it < 3; it++)
                    cp_async16(b_dst[it] + nb * B_BUF_BYTES,
                               b_src[it] + (ch + 1) * 16);
                cp_commit();
                cp_wait<1>();
            } else {
                cp_wait<0>();
            }
            __syncthreads();
#pragma unroll
            for (int kp2 = 0; kp2 < 8; kp2++) {
                ulonglong2 av[4], bv[6];
#pragma unroll
                for (int i = 0; i < 4; i++)
                    av[i] = *(const ulonglong2*)&a_s[buf][ty + 16 * i][2 * kp2];
#pragma unroll
                for (int j2 = 0; j2 < 6; j2++)
                    bv[j2] = *(const ulonglong2*)&b_s[buf][tx + 16 * j2][2 * kp2];
#pragma unroll
                for (int i = 0; i < 4; i++)
#pragma unroll
                    for (int j2 = 0; j2 < 6; j2++) {
                        acc[i][j2] = fma2(av[i].x, bv[j2].x, acc[i][j2]);
                        acc[i][j2] = fma2(av[i].y, bv[j2].y, acc[i][j2]);
                    }
            }
            __syncthreads();
        }

        const float* bih = b_ih + ((size_t)layer * 2 + d) * G3;
#pragma unroll
        for (int i = 0; i < 4; i++) {
            size_t row = row0 + ty + 16 * i;
#pragma unroll
            for (int j2 = 0; j2 < 6; j2++) {
                int c = c0 + tx + 16 * j2;
                float2 f = u2f2(acc[i][j2]);
                g_gx[((size_t)d * BL + row) * G3 + c] = f.x + f.y + bih[c];
            }
        }
        __syncthreads();
        if (tid == 0) {
            int* fp = g_flags +
                (((size_t)(layer - 1) * 2 + d) * Bsz + b) * NTILE + (t0 >> 6);
            asm volatile("red.release.gpu.global.add.s32 [%0], 1;"
                         :: "l"(fp) : "memory");
        }
        return;
    }

    // =================== SCAN consumer (R14/R11 core) ===================
    const int b = blockIdx.x;
    const int d = tid >> 7;
    const int j = (tid & 127) >> 1;
    const int half = tid & 1;
    const unsigned barid = 1 + d;

    const size_t base = ((size_t)layer * 2 + d) * G3;
    const ull* Wr = (const ull*)w_hh + (base + j) * 32 + half * 16;
    const ull* Wz = (const ull*)w_hh + (base + 64 + j) * 32 + half * 16;
    const ull* Wn = (const ull*)w_hh + (base + 128 + j) * 32 + half * 16;
    ull wr[16], wz[16], wn[16];
#pragma unroll
    for (int i = 0; i < 16; i++) { wr[i] = Wr[i]; wz[i] = Wz[i]; wn[i] = Wn[i]; }
    const float br = b_hh[base + j];
    const float bz = b_hh[base + 64 + j];
    const float bn = b_hh[base + 128 + j];

    if ((tid & 127) < Hd) h_s[d][0][tid & 127] = 0.0f;
    float hreg = 0.0f;

    const int t0 = (d == 0) ? 0 : (Lseq - 1);
    const int tstep = (d == 0) ? 1 : -1;
    const long gstep = (long)tstep * G3;

    const float* gp = g_gx + (((size_t)d * Bsz + b) * Lseq + t0) * G3 + j;
    float* outp = out_g + (size_t)b * Lseq * IN2H + d * Hd + j;
    const int* fl = g_flags + (((size_t)(layer - 1) * 2 + d) * Bsz + b) * NTILE;

    asm volatile("bar.sync %0, %1;" :: "r"(barid), "r"(128) : "memory");

    float qr0 = 0.f, qz0 = 0.f, qn0 = 0.f;
    float qr1 = 0.f, qz1 = 0.f, qn1 = 0.f;
    if (half == 0) {
        wait_flag(fl + (d ? (NTILE - 1) : 0));   // tile containing steps 0,1
        qr0 = gp[0];     qz0 = gp[64];          qn0 = gp[128];
        qr1 = gp[gstep]; qz1 = gp[gstep + 64];  qn1 = gp[gstep + 128];
    }

#define SCAN_STEP(PR, S)                                                      \
    {                                                                         \
        const int s_ = (S);                                                   \
        float rawr = qr##PR, rawz = qz##PR, rawn = qn##PR;                    \
        const int sp_ = s_ + 2;                                               \
        if (half == 0 && sp_ < Lseq) {                                        \
            if ((sp_ & 63) == 0)                                              \
                wait_flag(fl + (d ? (NTILE - 1 - (sp_ >> 6)) : (sp_ >> 6)));  \
            qr##PR = gp[(long)sp_ * gstep];                                   \
            qz##PR = gp[(long)sp_ * gstep + 64];                              \
            qn##PR = gp[(long)sp_ * gstep + 128];                             \
        }                                                                     \
        const ulonglong2* h4_ =                                               \
            (const ulonglong2*)(h_s[d][PR] + half * 32);                      \
        ull r0 = 0, r1 = 0, z0 = 0, z1 = 0, n0 = 0, n1 = 0;                   \
        _Pragma("unroll")                                                     \
        for (int i = 0; i < 4; i++) {                                         \
            ulonglong2 u = h4_[2 * i];                                        \
            ulonglong2 v = h4_[2 * i + 1];                                    \
            r0 = fma2(wr[4 * i + 0], u.x, r0);                                \
            r1 = fma2(wr[4 * i + 1], u.y, r1);                                \
            z0 = fma2(wz[4 * i + 0], u.x, z0);                                \
            z1 = fma2(wz[4 * i + 1], u.y, z1);                                \
            n0 = fma2(wn[4 * i + 0], u.x, n0);                                \
            n1 = fma2(wn[4 * i + 1], u.y, n1);                                \
            r0 = fma2(wr[4 * i + 2], v.x, r0);                                \
            r1 = fma2(wr[4 * i + 3], v.y, r1);                                \
            z0 = fma2(wz[4 * i + 2], v.x, z0);                                \
            z1 = fma2(wz[4 * i + 3], v.y, z1);                                \
            n0 = fma2(wn[4 * i + 2], v.x, n0);                                \
            n1 = fma2(wn[4 * i + 3], v.y, n1);                                \
        }                                                                     \
        float2 fr0 = u2f2(r0), fr1 = u2f2(r1);                                \
        float2 fz0 = u2f2(z0), fz1 = u2f2(z1);                                \
        float2 fn0 = u2f2(n0), fn1 = u2f2(n1);                                \
        float pgr = (fr0.x + fr0.y) + (fr1.x + fr1.y);                        \
        float pgz = (fz0.x + fz0.y) + (fz1.x + fz1.y);                        \
        float pgn = (fn0.x + fn0.y) + (fn1.x + fn1.y);                        \
        pgr += __shfl_xor_sync(0xFFFFFFFFu, pgr, 1);                          \
        pgz += __shfl_xor_sync(0xFFFFFFFFu, pgz, 1);                          \
        pgn += __shfl_xor_sync(0xFFFFFFFFu, pgn, 1);                          \
        if (half == 0) {                                                      \
            float r_ = sigm_fast(rawr + pgr + br);                            \
            float z_ = sigm_fast(rawz + pgz + bz);                            \
            float n_ = tanh_fast(fmaf(r_, pgn + bn, rawn));                   \
            float hn = fmaf(z_, hreg - n_, n_);                               \
            hreg = hn;                                                        \
            h_s[d][1 - (PR)][j] = hn;                                         \
            outp[(size_t)(t0 + s_ * tstep) * IN2H] = hn;                      \
        }                                                                     \
        asm volatile("bar.sync %0, %1;" :: "r"(barid), "r"(128) : "memory");  \
    }

#pragma unroll 1
    for (int s0 = 0; s0 < Lseq; s0 += 2) {
        SCAN_STEP(0, s0)
        SCAN_STEP(1, s0 + 1)
    }
#undef SCAN_STEP
}

// ---------------- final FC on last timestep ----------------
__global__ void fc_kernel(const float* __restrict__ fc_w,
                          const float* __restrict__ fc_b,
                          const float* __restrict__ hbuf,
                          float* __restrict__ out) {
    int b = blockIdx.x;
    int c = threadIdx.x;
    __shared__ float last[IN2H];
    if (threadIdx.x < IN2H)
        last[threadIdx.x] =
            hbuf[((size_t)b * Lseq + (Lseq - 1)) * IN2H + threadIdx.x];
    __syncthreads();
    if (c < NCLS) {
        float s = fc_b[c];
        const float* w = fc_w + (size_t)c * IN2H;
#pragma unroll 8
        for (int k = 0; k < IN2H; k++) s += last[k] * w[k];
        out[(size_t)b * NCLS + c] = s;
    }
}

extern "C" void kernel_launch(void* const* d_in, const int* in_sizes, int n_in,
                              void* d_out, int out_size) {
    const float* x     = (const float*)d_in[0];
    const float* w_ih0 = (const float*)d_in[1];
    const float* w_ih  = (const float*)d_in[2];
    const float* w_hh  = (const float*)d_in[3];
    const float* b_ih  = (const float*)d_in[4];
    const float* b_hh  = (const float*)d_in[5];
    const float* fc_w  = (const float*)d_in[6];
    const float* fc_b  = (const float*)d_in[7];
    float* out = (float*)d_out;

    float* bufA;
    float* bufB;
    cudaGetSymbolAddress((void**)&bufA, g_bufA);
    cudaGetSymbolAddress((void**)&bufB, g_bufB);

    zero_flags_kernel<<<(3 * 2 * Bsz * NTILE + 255) / 256, 256>>>();

    // layer 0: x -> bufA (no gx GEMM)
    scan0_kernel<<<Bsz, 256>>>(w_hh, b_hh, x, w_ih0, b_ih, bufA);
    // layers 1..3: scan blocks first, then gemm producer blocks
    layer_kernel<<<Bsz + NGEMM, 256>>>(w_hh, b_hh, b_ih, w_ih, bufA, bufB, 1);
    layer_kernel<<<Bsz + NGEMM, 256>>>(w_hh, b_hh, b_ih, w_ih, bufB, bufA, 2);
    layer_kernel<<<Bsz + NGEMM, 256>>>(w_hh, b_hh, b_ih, w_ih, bufA, bufB, 3);

    fc_kernel<<<Bsz, 256>>>(fc_w, fc_b, bufB, out);
}